// round 2
// baseline (speedup 1.0000x reference)
#include <cuda_runtime.h>
#include <cstdint>

#define BB 32
#define TS 512
#define TL 2048
#define DD 256
#define NEGV (-1e9f)

// ---------------- scratch (static device memory; no allocations) ----------------
__device__ float g_simT[(size_t)BB * TL * TS];   // [b, l, s] transposed similarity for coalesced DP reads
__device__ float g_invlip[BB * TL];              // 1/||lip||
__device__ float g_ft[BB * TS];                  // 1/(||phon||+1)
__device__ int   g_begins[BB * TS];
__device__ int   g_ends[BB * TS];
__device__ float g_cofs[BB];
__device__ float g_meancof;
__device__ int   g_idx[BB * TL];                 // backtracked path index per (b, j)

// ---------------- stats: cof, lip_targets, begins/ends ----------------
__global__ void stats_kernel(const int* __restrict__ d_targets,
                             const int* __restrict__ lip_lens) {
    const int b = blockIdx.x;
    const int t = threadIdx.x;
    __shared__ int   s_int[TS];
    __shared__ float s_sum[TS];
    __shared__ float s_val[TS];
    __shared__ int   s_idx[TS];
    __shared__ float sh_cof, sh_dif;
    __shared__ int   sh_maxidx;

    const int d = d_targets[b * TS + t];
    const int L = lip_lens[b];

    // sum of d_targets
    s_int[t] = d;
    __syncthreads();
    for (int off = TS / 2; off > 0; off >>= 1) {
        if (t < off) s_int[t] += s_int[t + off];
        __syncthreads();
    }
    if (t == 0) sh_cof = __fdiv_rn((float)s_int[0], (float)L);
    __syncthreads();
    const float cof = sh_cof;

    // lip_targets = round(d / cof)   (round half-to-even, like jnp.round)
    float lt = rintf(__fdiv_rn((float)d, cof));

    // sum(lt) and first-occurrence argmax(lt)
    s_sum[t] = lt;
    s_val[t] = lt;
    s_idx[t] = t;
    __syncthreads();
    for (int off = TS / 2; off > 0; off >>= 1) {
        if (t < off) {
            s_sum[t] += s_sum[t + off];
            float v2 = s_val[t + off];
            int   i2 = s_idx[t + off];
            if (v2 > s_val[t] || (v2 == s_val[t] && i2 < s_idx[t])) {
                s_val[t] = v2;
                s_idx[t] = i2;
            }
        }
        __syncthreads();
    }
    if (t == 0) {
        sh_dif = (float)L - s_sum[0];
        sh_maxidx = s_idx[0];
    }
    __syncthreads();
    if (t == sh_maxidx) lt += sh_dif;

    // inclusive cumsum of (int)lt
    const int lti = (int)lt;   // trunc toward zero like .astype(int32)
    s_int[t] = lti;
    __syncthreads();
    for (int off = 1; off < TS; off <<= 1) {
        int add = (t >= off) ? s_int[t - off] : 0;
        __syncthreads();
        s_int[t] += add;
        __syncthreads();
    }
    const int e = s_int[t];
    g_ends[b * TS + t]   = e;
    g_begins[b * TS + t] = e - lti;
    if (t == 0) g_cofs[b] = cof;
}

__global__ void meancof_kernel() {
    const int lane = threadIdx.x;
    float v = g_cofs[lane];
    for (int o = 16; o; o >>= 1) v += __shfl_xor_sync(0xffffffffu, v, o);
    if (lane == 0) g_meancof = __fdiv_rn(v, 32.0f);
}

// ---------------- row norms ----------------
__global__ void lipnorm_kernel(const float* __restrict__ lip) {
    const int warp = (blockIdx.x * blockDim.x + threadIdx.x) >> 5;
    const int lane = threadIdx.x & 31;
    if (warp >= BB * TL) return;
    const float4* p = (const float4*)(lip + (size_t)warp * DD);
    float s = 0.0f;
#pragma unroll
    for (int i = 0; i < 2; i++) {
        float4 v = p[lane + i * 32];
        s += v.x * v.x + v.y * v.y + v.z * v.z + v.w * v.w;
    }
    for (int o = 16; o; o >>= 1) s += __shfl_xor_sync(0xffffffffu, s, o);
    if (lane == 0) g_invlip[warp] = __fdiv_rn(1.0f, __fsqrt_rn(s));
}

__global__ void textnorm_kernel(const float* __restrict__ phon) {
    const int warp = (blockIdx.x * blockDim.x + threadIdx.x) >> 5;
    const int lane = threadIdx.x & 31;
    if (warp >= BB * TS) return;
    const float4* p = (const float4*)(phon + (size_t)warp * DD);
    float s = 0.0f;
#pragma unroll
    for (int i = 0; i < 2; i++) {
        float4 v = p[lane + i * 32];
        s += v.x * v.x + v.y * v.y + v.z * v.z + v.w * v.w;
    }
    for (int o = 16; o; o >>= 1) s += __shfl_xor_sync(0xffffffffu, s, o);
    if (lane == 0) g_ft[warp] = __fdiv_rn(1.0f, __fadd_rn(__fsqrt_rn(s), 1.0f));
}

// ---------------- fp32 SGEMM: sim[b,s,l] = dot(phon[b,s,:], lip[b,l,:]) * ft * invlip ----------------
__global__ __launch_bounds__(256) void gemm_kernel(const float* __restrict__ lip,
                                                   const float* __restrict__ phon,
                                                   float* __restrict__ sim) {
    const int b  = blockIdx.z;
    const int l0 = blockIdx.x * 64;
    const int s0 = blockIdx.y * 64;
    __shared__ float As[16][72];   // [k][s]
    __shared__ float Bs[16][72];   // [k][l]
    const int t  = threadIdx.x;
    const int tx = t & 15;         // l micro
    const int ty = t >> 4;         // s micro
    const int lr = t >> 2;         // 0..63 row-in-tile for loads
    const int lc = (t & 3) * 4;    // k sub-offset

    float acc[4][4];
#pragma unroll
    for (int i = 0; i < 4; i++)
#pragma unroll
        for (int j = 0; j < 4; j++) acc[i][j] = 0.0f;

    const float* Ap = phon + ((size_t)(b * TS + s0 + lr) * DD) + lc;
    const float* Bp = lip  + ((size_t)(b * TL + l0 + lr) * DD) + lc;

    for (int k0 = 0; k0 < DD; k0 += 16) {
        float4 av = *(const float4*)(Ap + k0);
        float4 bv = *(const float4*)(Bp + k0);
        As[lc + 0][lr] = av.x; As[lc + 1][lr] = av.y;
        As[lc + 2][lr] = av.z; As[lc + 3][lr] = av.w;
        Bs[lc + 0][lr] = bv.x; Bs[lc + 1][lr] = bv.y;
        Bs[lc + 2][lr] = bv.z; Bs[lc + 3][lr] = bv.w;
        __syncthreads();
#pragma unroll
        for (int k = 0; k < 16; k++) {
            float4 a = *(const float4*)&As[k][ty * 4];
            float4 bq = *(const float4*)&Bs[k][tx * 4];
            acc[0][0] += a.x * bq.x; acc[0][1] += a.x * bq.y; acc[0][2] += a.x * bq.z; acc[0][3] += a.x * bq.w;
            acc[1][0] += a.y * bq.x; acc[1][1] += a.y * bq.y; acc[1][2] += a.y * bq.z; acc[1][3] += a.y * bq.w;
            acc[2][0] += a.z * bq.x; acc[2][1] += a.z * bq.y; acc[2][2] += a.z * bq.z; acc[2][3] += a.z * bq.w;
            acc[3][0] += a.w * bq.x; acc[3][1] += a.w * bq.y; acc[3][2] += a.w * bq.z; acc[3][3] += a.w * bq.w;
        }
        __syncthreads();
    }

    float fa[4], fb[4];
#pragma unroll
    for (int i = 0; i < 4; i++) fa[i] = g_ft[b * TS + s0 + ty * 4 + i];
#pragma unroll
    for (int j = 0; j < 4; j++) fb[j] = g_invlip[b * TL + l0 + tx * 4 + j];
#pragma unroll
    for (int i = 0; i < 4; i++)
#pragma unroll
        for (int j = 0; j < 4; j++) acc[i][j] = acc[i][j] * fa[i] * fb[j];

    // sim [b, s, l]
#pragma unroll
    for (int i = 0; i < 4; i++) {
        float4 st = make_float4(acc[i][0], acc[i][1], acc[i][2], acc[i][3]);
        *(float4*)(sim + ((size_t)(b * TS + s0 + ty * 4 + i) * TL) + l0 + tx * 4) = st;
    }
    // simT [b, l, s]
#pragma unroll
    for (int j = 0; j < 4; j++) {
        float4 st = make_float4(acc[0][j], acc[1][j], acc[2][j], acc[3][j]);
        *(float4*)(g_simT + ((size_t)(b * TL + l0 + tx * 4 + j) * TS) + s0 + ty * 4) = st;
    }
}

// ---------------- monotonic alignment search: 1 warp per batch ----------------
__global__ __launch_bounds__(32) void dp_kernel(const int* __restrict__ src_lens,
                                                const int* __restrict__ lip_lens,
                                                float* __restrict__ out_dpred) {
    extern __shared__ unsigned short dirs[];   // [TL][32] packed stay bits (16 x per lane)
    __shared__ unsigned hist[TS];

    const int b = blockIdx.x;
    const int lane = threadIdx.x;
    const int srcLen = src_lens[b];
    const int lipLen = lip_lens[b];
    const int xb = lane * 16;

    unsigned xmask = 0;
#pragma unroll
    for (int k = 0; k < 16; k++)
        if (xb + k < srcLen) xmask |= (1u << k);

    float v[16];
#pragma unroll
    for (int k = 0; k < 16; k++) v[k] = 0.0f;

    const float4* rowbase = (const float4*)(g_simT + (size_t)b * TL * TS);
    const int fo = lane * 4;   // float4 offset within row

    const int PF = 8;
    float4 buf[PF][4];
#pragma unroll
    for (int u = 0; u < PF; u++)
#pragma unroll
        for (int q = 0; q < 4; q++) buf[u][q] = rowbase[u * 128 + fo + q];

    for (int j0 = 0; j0 < TL; j0 += PF) {
#pragma unroll
        for (int u = 0; u < PF; u++) {
            const int j = j0 + u;
            const bool jv = (j < lipLen);
            float val[16];
#pragma unroll
            for (int q = 0; q < 4; q++) {
                val[q * 4 + 0] = buf[u][q].x;
                val[q * 4 + 1] = buf[u][q].y;
                val[q * 4 + 2] = buf[u][q].z;
                val[q * 4 + 3] = buf[u][q].w;
            }
            const int jn = j + PF;
            if (jn < TL) {
#pragma unroll
                for (int q = 0; q < 4; q++) buf[u][q] = rowbase[jn * 128 + fo + q];
            }

            float last = v[15];
            float up = __shfl_up_sync(0xffffffffu, last, 1);
            float pv = (lane == 0) ? NEGV : up;
            unsigned bits = 0;
            const int tj = j - xb;   // k <= tj  <=>  x <= j
#pragma unroll
            for (int k = 0; k < 16; k++) {
                const bool xv = ((xmask >> k) & 1u) != 0;
                const float vk = (jv && xv) ? val[k] : 0.0f;
                const float cur = v[k];
                const bool stay = (cur >= pv);
                const float vm = stay ? cur : pv;
                float nv = vm + vk;
                nv = (k <= tj) ? nv : NEGV;
                const bool sm = stay || !(jv && xv);
                bits |= (sm ? 1u : 0u) << k;
                pv = cur;
                v[k] = nv;
            }
            dirs[j * 32 + lane] = (unsigned short)bits;
        }
    }

    for (int x = lane; x < TS; x += 32) hist[x] = 0;
    __syncwarp();

    if (lane == 0) {
        int idx = srcLen - 1;
        int* gi = g_idx + b * TL;
        for (int j = TL - 1; j >= 0; j--) {
            gi[j] = idx;
            if (j < lipLen) hist[idx]++;
            unsigned short w = dirs[j * 32 + (idx >> 4)];
            idx += (int)((w >> (idx & 15)) & 1u) - 1;
        }
    }
    __syncwarp();

    const float mc = g_meancof;
    for (int x = lane; x < TS; x += 32)
        out_dpred[b * TS + x] = (float)hist[x] * mc;
}

// ---------------- fill gt_similarity and alignment ----------------
__global__ __launch_bounds__(256) void fill_kernel(const int* __restrict__ lip_lens,
                                                   float* __restrict__ gt,
                                                   float* __restrict__ align) {
    const int b = blockIdx.z;
    const int s = blockIdx.y;
    const int l = (blockIdx.x * 256 + threadIdx.x) * 4;
    const int bg = g_begins[b * TS + s];
    const int en = g_ends[b * TS + s];
    const int lipLen = lip_lens[b];
    const int* idxp = g_idx + b * TL + l;

    float4 gq, aq;
    int i0 = idxp[0], i1 = idxp[1], i2 = idxp[2], i3 = idxp[3];
    gq.x = (l + 0 >= bg && l + 0 < en) ? 1.0f : 0.0f;
    gq.y = (l + 1 >= bg && l + 1 < en) ? 1.0f : 0.0f;
    gq.z = (l + 2 >= bg && l + 2 < en) ? 1.0f : 0.0f;
    gq.w = (l + 3 >= bg && l + 3 < en) ? 1.0f : 0.0f;
    aq.x = (l + 0 < lipLen && i0 == s) ? 1.0f : 0.0f;
    aq.y = (l + 1 < lipLen && i1 == s) ? 1.0f : 0.0f;
    aq.z = (l + 2 < lipLen && i2 == s) ? 1.0f : 0.0f;
    aq.w = (l + 3 < lipLen && i3 == s) ? 1.0f : 0.0f;

    const size_t off = ((size_t)(b * TS + s) * TL) + l;
    *(float4*)(gt + off) = gq;
    *(float4*)(align + off) = aq;
}

// ---------------- launch ----------------
extern "C" void kernel_launch(void* const* d_in, const int* in_sizes, int n_in,
                              void* d_out, int out_size) {
    const float* lip  = (const float*)d_in[0];
    const float* phon = (const float*)d_in[1];
    const int*   dtg  = (const int*)d_in[2];
    const int*   srcl = (const int*)d_in[3];
    const int*   lipl = (const int*)d_in[4];

    float* out = (float*)d_out;
    const size_t big = (size_t)BB * TS * TL;
    float* sim = out;
    float* gt  = out + big;
    float* al  = out + 2 * big;
    float* dp  = out + 3 * big;

    cudaFuncSetAttribute(dp_kernel, cudaFuncAttributeMaxDynamicSharedMemorySize, 136 * 1024);

    stats_kernel<<<BB, TS>>>(dtg, lipl);
    meancof_kernel<<<1, 32>>>();
    lipnorm_kernel<<<(BB * TL) / 8, 256>>>(lip);
    textnorm_kernel<<<(BB * TS) / 8, 256>>>(phon);
    gemm_kernel<<<dim3(TL / 64, TS / 64, BB), 256>>>(lip, phon, sim);
    dp_kernel<<<BB, 32, TL * 32 * sizeof(unsigned short)>>>(srcl, lipl, dp);
    fill_kernel<<<dim3(TL / 1024, TS, BB), 256>>>(lipl, gt, al);
}

// round 3
// speedup vs baseline: 1.0944x; 1.0944x over previous
#include <cuda_runtime.h>
#include <cstdint>

#define BB 32
#define TS 512
#define TL 2048
#define DD 256
#define NEGV (-1e9f)

// ---------------- scratch (static device memory; no allocations) ----------------
__device__ float g_simT[(size_t)BB * TL * TS];   // [b, l, s] transposed similarity for coalesced DP reads
__device__ float g_invlip[BB * TL];              // 1/||lip||
__device__ float g_ft[BB * TS];                  // 1/(||phon||+1)
__device__ int   g_begins[BB * TS];
__device__ int   g_ends[BB * TS];
__device__ float g_cofs[BB];
__device__ float g_meancof;
__device__ int   g_idx[BB * TL];                 // backtracked path index per (b, j)

// ---------------- stats: cof, lip_targets, begins/ends ----------------
__global__ void stats_kernel(const int* __restrict__ d_targets,
                             const int* __restrict__ lip_lens) {
    const int b = blockIdx.x;
    const int t = threadIdx.x;
    __shared__ int   s_int[TS];
    __shared__ float s_sum[TS];
    __shared__ float s_val[TS];
    __shared__ int   s_idx[TS];
    __shared__ float sh_cof, sh_dif;
    __shared__ int   sh_maxidx;

    const int d = d_targets[b * TS + t];
    const int L = lip_lens[b];

    // sum of d_targets
    s_int[t] = d;
    __syncthreads();
    for (int off = TS / 2; off > 0; off >>= 1) {
        if (t < off) s_int[t] += s_int[t + off];
        __syncthreads();
    }
    if (t == 0) sh_cof = __fdiv_rn((float)s_int[0], (float)L);
    __syncthreads();
    const float cof = sh_cof;

    // lip_targets = round(d / cof)   (round half-to-even, like jnp.round)
    float lt = rintf(__fdiv_rn((float)d, cof));

    // sum(lt) and first-occurrence argmax(lt)
    s_sum[t] = lt;
    s_val[t] = lt;
    s_idx[t] = t;
    __syncthreads();
    for (int off = TS / 2; off > 0; off >>= 1) {
        if (t < off) {
            s_sum[t] += s_sum[t + off];
            float v2 = s_val[t + off];
            int   i2 = s_idx[t + off];
            if (v2 > s_val[t] || (v2 == s_val[t] && i2 < s_idx[t])) {
                s_val[t] = v2;
                s_idx[t] = i2;
            }
        }
        __syncthreads();
    }
    if (t == 0) {
        sh_dif = (float)L - s_sum[0];
        sh_maxidx = s_idx[0];
    }
    __syncthreads();
    if (t == sh_maxidx) lt += sh_dif;

    // inclusive cumsum of (int)lt
    const int lti = (int)lt;   // trunc toward zero like .astype(int32)
    s_int[t] = lti;
    __syncthreads();
    for (int off = 1; off < TS; off <<= 1) {
        int add = (t >= off) ? s_int[t - off] : 0;
        __syncthreads();
        s_int[t] += add;
        __syncthreads();
    }
    const int e = s_int[t];
    g_ends[b * TS + t]   = e;
    g_begins[b * TS + t] = e - lti;
    if (t == 0) g_cofs[b] = cof;
}

__global__ void meancof_kernel() {
    const int lane = threadIdx.x;
    float v = g_cofs[lane];
    for (int o = 16; o; o >>= 1) v += __shfl_xor_sync(0xffffffffu, v, o);
    if (lane == 0) g_meancof = __fdiv_rn(v, 32.0f);
}

// ---------------- row norms ----------------
__global__ void lipnorm_kernel(const float* __restrict__ lip) {
    const int warp = (blockIdx.x * blockDim.x + threadIdx.x) >> 5;
    const int lane = threadIdx.x & 31;
    if (warp >= BB * TL) return;
    const float4* p = (const float4*)(lip + (size_t)warp * DD);
    float s = 0.0f;
#pragma unroll
    for (int i = 0; i < 2; i++) {
        float4 v = p[lane + i * 32];
        s += v.x * v.x + v.y * v.y + v.z * v.z + v.w * v.w;
    }
    for (int o = 16; o; o >>= 1) s += __shfl_xor_sync(0xffffffffu, s, o);
    if (lane == 0) g_invlip[warp] = __fdiv_rn(1.0f, __fsqrt_rn(s));
}

__global__ void textnorm_kernel(const float* __restrict__ phon) {
    const int warp = (blockIdx.x * blockDim.x + threadIdx.x) >> 5;
    const int lane = threadIdx.x & 31;
    if (warp >= BB * TS) return;
    const float4* p = (const float4*)(phon + (size_t)warp * DD);
    float s = 0.0f;
#pragma unroll
    for (int i = 0; i < 2; i++) {
        float4 v = p[lane + i * 32];
        s += v.x * v.x + v.y * v.y + v.z * v.z + v.w * v.w;
    }
    for (int o = 16; o; o >>= 1) s += __shfl_xor_sync(0xffffffffu, s, o);
    if (lane == 0) g_ft[warp] = __fdiv_rn(1.0f, __fadd_rn(__fsqrt_rn(s), 1.0f));
}

// ---------------- fp32 SGEMM 128x128x8, 8x8 micro, double buffered ----------------
// sim[b,s,l] = dot(phon[b,s,:], lip[b,l,:]) * ft[s] * invlip[l]
__global__ __launch_bounds__(256, 2) void gemm_kernel(const float* __restrict__ lip,
                                                      const float* __restrict__ phon,
                                                      float* __restrict__ sim) {
    const int b  = blockIdx.z;
    const int l0 = blockIdx.x * 128;   // N tile (lip rows)
    const int s0 = blockIdx.y * 128;   // M tile (phoneme rows)

    __shared__ float As[2][8][132];    // [buf][k][m]
    __shared__ float Bs[2][8][132];    // [buf][k][n]

    const int t  = threadIdx.x;
    const int tx = t & 15;             // n micro (0..15) -> 8 l each
    const int ty = t >> 4;             // m micro (0..15) -> 8 s each
    const int lr = t >> 1;             // 0..127 row for global loads
    const int lc = (t & 1) * 4;        // k sub-offset (0 or 4)

    const float* Ap = phon + ((size_t)(b * TS + s0 + lr) * DD) + lc;
    const float* Bp = lip  + ((size_t)(b * TL + l0 + lr) * DD) + lc;

    float acc[8][8];
#pragma unroll
    for (int i = 0; i < 8; i++)
#pragma unroll
        for (int j = 0; j < 8; j++) acc[i][j] = 0.0f;

    // preload k-slab 0
    {
        float4 av = *(const float4*)(Ap);
        float4 bv = *(const float4*)(Bp);
        As[0][lc + 0][lr] = av.x; As[0][lc + 1][lr] = av.y;
        As[0][lc + 2][lr] = av.z; As[0][lc + 3][lr] = av.w;
        Bs[0][lc + 0][lr] = bv.x; Bs[0][lc + 1][lr] = bv.y;
        Bs[0][lc + 2][lr] = bv.z; Bs[0][lc + 3][lr] = bv.w;
    }
    __syncthreads();

    const int NKT = DD / 8;   // 32 slabs
#pragma unroll 1
    for (int kt = 0; kt < NKT; kt++) {
        float4 av, bv;
        const bool more = (kt + 1 < NKT);
        if (more) {
            av = *(const float4*)(Ap + (kt + 1) * 8);
            bv = *(const float4*)(Bp + (kt + 1) * 8);
        }
        const int cur = kt & 1;
#pragma unroll
        for (int k = 0; k < 8; k++) {
            float a[8], bb[8];
            *(float4*)&a[0]  = *(const float4*)&As[cur][k][ty * 8];
            *(float4*)&a[4]  = *(const float4*)&As[cur][k][ty * 8 + 4];
            *(float4*)&bb[0] = *(const float4*)&Bs[cur][k][tx * 8];
            *(float4*)&bb[4] = *(const float4*)&Bs[cur][k][tx * 8 + 4];
#pragma unroll
            for (int i = 0; i < 8; i++)
#pragma unroll
                for (int j = 0; j < 8; j++) acc[i][j] += a[i] * bb[j];
        }
        if (more) {
            const int nxt = cur ^ 1;
            As[nxt][lc + 0][lr] = av.x; As[nxt][lc + 1][lr] = av.y;
            As[nxt][lc + 2][lr] = av.z; As[nxt][lc + 3][lr] = av.w;
            Bs[nxt][lc + 0][lr] = bv.x; Bs[nxt][lc + 1][lr] = bv.y;
            Bs[nxt][lc + 2][lr] = bv.z; Bs[nxt][lc + 3][lr] = bv.w;
            __syncthreads();
        }
    }

    float fa[8], fb[8];
#pragma unroll
    for (int i = 0; i < 8; i++) fa[i] = g_ft[b * TS + s0 + ty * 8 + i];
#pragma unroll
    for (int j = 0; j < 8; j++) fb[j] = g_invlip[b * TL + l0 + tx * 8 + j];
#pragma unroll
    for (int i = 0; i < 8; i++)
#pragma unroll
        for (int j = 0; j < 8; j++) acc[i][j] = acc[i][j] * fa[i] * fb[j];

    // sim [b, s, l]
#pragma unroll
    for (int i = 0; i < 8; i++) {
        float* row = sim + ((size_t)(b * TS + s0 + ty * 8 + i) * TL) + l0 + tx * 8;
        *(float4*)(row)     = make_float4(acc[i][0], acc[i][1], acc[i][2], acc[i][3]);
        *(float4*)(row + 4) = make_float4(acc[i][4], acc[i][5], acc[i][6], acc[i][7]);
    }
    // simT [b, l, s]
#pragma unroll
    for (int j = 0; j < 8; j++) {
        float* row = g_simT + ((size_t)(b * TL + l0 + tx * 8 + j) * TS) + s0 + ty * 8;
        *(float4*)(row)     = make_float4(acc[0][j], acc[1][j], acc[2][j], acc[3][j]);
        *(float4*)(row + 4) = make_float4(acc[4][j], acc[5][j], acc[6][j], acc[7][j]);
    }
}

// ---------------- monotonic alignment search: 1 warp per batch ----------------
__global__ __launch_bounds__(32) void dp_kernel(const int* __restrict__ src_lens,
                                                const int* __restrict__ lip_lens,
                                                float* __restrict__ out_dpred) {
    extern __shared__ unsigned short dirs[];   // [TL][32] packed stay bits (16 x per lane)
    __shared__ unsigned hist[TS];

    const int b = blockIdx.x;
    const int lane = threadIdx.x;
    const int srcLen = src_lens[b];
    const int lipLen = lip_lens[b];
    const int xb = lane * 16;

    unsigned xmask = 0;
#pragma unroll
    for (int k = 0; k < 16; k++)
        if (xb + k < srcLen) xmask |= (1u << k);

    float v[16];
#pragma unroll
    for (int k = 0; k < 16; k++) v[k] = 0.0f;

    const float4* rowbase = (const float4*)(g_simT + (size_t)b * TL * TS);
    const int fo = lane * 4;   // float4 offset within row

    const int PF = 8;
    float4 buf[PF][4];
#pragma unroll
    for (int u = 0; u < PF; u++)
#pragma unroll
        for (int q = 0; q < 4; q++) buf[u][q] = rowbase[u * 128 + fo + q];

    for (int j0 = 0; j0 < TL; j0 += PF) {
#pragma unroll
        for (int u = 0; u < PF; u++) {
            const int j = j0 + u;
            const bool jv = (j < lipLen);
            float val[16];
#pragma unroll
            for (int q = 0; q < 4; q++) {
                val[q * 4 + 0] = buf[u][q].x;
                val[q * 4 + 1] = buf[u][q].y;
                val[q * 4 + 2] = buf[u][q].z;
                val[q * 4 + 3] = buf[u][q].w;
            }
            const int jn = j + PF;
            if (jn < TL) {
#pragma unroll
                for (int q = 0; q < 4; q++) buf[u][q] = rowbase[jn * 128 + fo + q];
            }

            float last = v[15];
            float up = __shfl_up_sync(0xffffffffu, last, 1);
            float pv = (lane == 0) ? NEGV : up;
            unsigned bits = 0;
            const int tj = j - xb;   // k <= tj  <=>  x <= j
#pragma unroll
            for (int k = 0; k < 16; k++) {
                const bool xv = ((xmask >> k) & 1u) != 0;
                const float vk = (jv && xv) ? val[k] : 0.0f;
                const float cur = v[k];
                const bool stay = (cur >= pv);
                const float vm = stay ? cur : pv;
                float nv = vm + vk;
                nv = (k <= tj) ? nv : NEGV;
                const bool sm = stay || !(jv && xv);
                bits |= (sm ? 1u : 0u) << k;
                pv = cur;
                v[k] = nv;
            }
            dirs[j * 32 + lane] = (unsigned short)bits;
        }
    }

    for (int x = lane; x < TS; x += 32) hist[x] = 0;
    __syncwarp();

    if (lane == 0) {
        int idx = srcLen - 1;
        int* gi = g_idx + b * TL;
        for (int j = TL - 1; j >= 0; j--) {
            gi[j] = idx;
            if (j < lipLen) hist[idx]++;
            unsigned short w = dirs[j * 32 + (idx >> 4)];
            idx += (int)((w >> (idx & 15)) & 1u) - 1;
        }
    }
    __syncwarp();

    const float mc = g_meancof;
    for (int x = lane; x < TS; x += 32)
        out_dpred[b * TS + x] = (float)hist[x] * mc;
}

// ---------------- fill gt_similarity and alignment ----------------
__global__ __launch_bounds__(256) void fill_kernel(const int* __restrict__ lip_lens,
                                                   float* __restrict__ gt,
                                                   float* __restrict__ align) {
    const int b = blockIdx.z;
    const int s = blockIdx.y;
    const int l = (blockIdx.x * 256 + threadIdx.x) * 4;
    const int bg = g_begins[b * TS + s];
    const int en = g_ends[b * TS + s];
    const int lipLen = lip_lens[b];
    const int4 iv = *(const int4*)(g_idx + b * TL + l);

    float4 gq, aq;
    gq.x = (l + 0 >= bg && l + 0 < en) ? 1.0f : 0.0f;
    gq.y = (l + 1 >= bg && l + 1 < en) ? 1.0f : 0.0f;
    gq.z = (l + 2 >= bg && l + 2 < en) ? 1.0f : 0.0f;
    gq.w = (l + 3 >= bg && l + 3 < en) ? 1.0f : 0.0f;
    aq.x = (l + 0 < lipLen && iv.x == s) ? 1.0f : 0.0f;
    aq.y = (l + 1 < lipLen && iv.y == s) ? 1.0f : 0.0f;
    aq.z = (l + 2 < lipLen && iv.z == s) ? 1.0f : 0.0f;
    aq.w = (l + 3 < lipLen && iv.w == s) ? 1.0f : 0.0f;

    const size_t off = ((size_t)(b * TS + s) * TL) + l;
    *(float4*)(gt + off) = gq;
    *(float4*)(align + off) = aq;
}

// ---------------- launch ----------------
extern "C" void kernel_launch(void* const* d_in, const int* in_sizes, int n_in,
                              void* d_out, int out_size) {
    const float* lip  = (const float*)d_in[0];
    const float* phon = (const float*)d_in[1];
    const int*   dtg  = (const int*)d_in[2];
    const int*   srcl = (const int*)d_in[3];
    const int*   lipl = (const int*)d_in[4];

    float* out = (float*)d_out;
    const size_t big = (size_t)BB * TS * TL;
    float* sim = out;
    float* gt  = out + big;
    float* al  = out + 2 * big;
    float* dp  = out + 3 * big;

    cudaFuncSetAttribute(dp_kernel, cudaFuncAttributeMaxDynamicSharedMemorySize, 136 * 1024);

    stats_kernel<<<BB, TS>>>(dtg, lipl);
    meancof_kernel<<<1, 32>>>();
    lipnorm_kernel<<<(BB * TL) / 8, 256>>>(lip);
    textnorm_kernel<<<(BB * TS) / 8, 256>>>(phon);
    gemm_kernel<<<dim3(TL / 128, TS / 128, BB), 256>>>(lip, phon, sim);
    dp_kernel<<<BB, 32, TL * 32 * sizeof(unsigned short)>>>(srcl, lipl, dp);
    fill_kernel<<<dim3(TL / 1024, TS, BB), 256>>>(lipl, gt, al);
}

// round 4
// speedup vs baseline: 1.2183x; 1.1132x over previous
#include <cuda_runtime.h>
#include <cstdint>

#define BB 32
#define TS 512
#define TL 2048
#define DD 256
#define NEGV (-1e9f)

// ---------------- scratch (static device memory; no allocations) ----------------
__device__ float g_simT[(size_t)BB * TL * TS];   // [b, l, s] transposed similarity for coalesced DP reads
__device__ float g_invlip[BB * TL];              // 1/||lip||
__device__ float g_ft[BB * TS];                  // 1/(||phon||+1)
__device__ int   g_begins[BB * TS];
__device__ int   g_ends[BB * TS];
__device__ float g_cofs[BB];
__device__ float g_meancof;
__device__ int   g_idx[BB * TL];                 // backtracked path index per (b, j)

// ---------------- stats: cof, lip_targets, begins/ends ----------------
__global__ void stats_kernel(const int* __restrict__ d_targets,
                             const int* __restrict__ lip_lens) {
    const int b = blockIdx.x;
    const int t = threadIdx.x;
    __shared__ int   s_int[TS];
    __shared__ float s_sum[TS];
    __shared__ float s_val[TS];
    __shared__ int   s_idx[TS];
    __shared__ float sh_cof, sh_dif;
    __shared__ int   sh_maxidx;

    const int d = d_targets[b * TS + t];
    const int L = lip_lens[b];

    s_int[t] = d;
    __syncthreads();
    for (int off = TS / 2; off > 0; off >>= 1) {
        if (t < off) s_int[t] += s_int[t + off];
        __syncthreads();
    }
    if (t == 0) sh_cof = __fdiv_rn((float)s_int[0], (float)L);
    __syncthreads();
    const float cof = sh_cof;

    float lt = rintf(__fdiv_rn((float)d, cof));

    s_sum[t] = lt;
    s_val[t] = lt;
    s_idx[t] = t;
    __syncthreads();
    for (int off = TS / 2; off > 0; off >>= 1) {
        if (t < off) {
            s_sum[t] += s_sum[t + off];
            float v2 = s_val[t + off];
            int   i2 = s_idx[t + off];
            if (v2 > s_val[t] || (v2 == s_val[t] && i2 < s_idx[t])) {
                s_val[t] = v2;
                s_idx[t] = i2;
            }
        }
        __syncthreads();
    }
    if (t == 0) {
        sh_dif = (float)L - s_sum[0];
        sh_maxidx = s_idx[0];
    }
    __syncthreads();
    if (t == sh_maxidx) lt += sh_dif;

    const int lti = (int)lt;
    s_int[t] = lti;
    __syncthreads();
    for (int off = 1; off < TS; off <<= 1) {
        int add = (t >= off) ? s_int[t - off] : 0;
        __syncthreads();
        s_int[t] += add;
        __syncthreads();
    }
    const int e = s_int[t];
    g_ends[b * TS + t]   = e;
    g_begins[b * TS + t] = e - lti;
    if (t == 0) g_cofs[b] = cof;
}

__global__ void meancof_kernel() {
    const int lane = threadIdx.x;
    float v = g_cofs[lane];
    for (int o = 16; o; o >>= 1) v += __shfl_xor_sync(0xffffffffu, v, o);
    if (lane == 0) g_meancof = __fdiv_rn(v, 32.0f);
}

// ---------------- row norms ----------------
__global__ void lipnorm_kernel(const float* __restrict__ lip) {
    const int warp = (blockIdx.x * blockDim.x + threadIdx.x) >> 5;
    const int lane = threadIdx.x & 31;
    if (warp >= BB * TL) return;
    const float4* p = (const float4*)(lip + (size_t)warp * DD);
    float s = 0.0f;
#pragma unroll
    for (int i = 0; i < 2; i++) {
        float4 v = p[lane + i * 32];
        s += v.x * v.x + v.y * v.y + v.z * v.z + v.w * v.w;
    }
    for (int o = 16; o; o >>= 1) s += __shfl_xor_sync(0xffffffffu, s, o);
    if (lane == 0) g_invlip[warp] = __fdiv_rn(1.0f, __fsqrt_rn(s));
}

__global__ void textnorm_kernel(const float* __restrict__ phon) {
    const int warp = (blockIdx.x * blockDim.x + threadIdx.x) >> 5;
    const int lane = threadIdx.x & 31;
    if (warp >= BB * TS) return;
    const float4* p = (const float4*)(phon + (size_t)warp * DD);
    float s = 0.0f;
#pragma unroll
    for (int i = 0; i < 2; i++) {
        float4 v = p[lane + i * 32];
        s += v.x * v.x + v.y * v.y + v.z * v.z + v.w * v.w;
    }
    for (int o = 16; o; o >>= 1) s += __shfl_xor_sync(0xffffffffu, s, o);
    if (lane == 0) g_ft[warp] = __fdiv_rn(1.0f, __fadd_rn(__fsqrt_rn(s), 1.0f));
}

// ---------------- fp32 SGEMM 128x128x8, split 4+4 micro-tile, double buffered ----------------
__global__ __launch_bounds__(256, 2) void gemm_kernel(const float* __restrict__ lip,
                                                      const float* __restrict__ phon,
                                                      float* __restrict__ sim) {
    const int b  = blockIdx.z;
    const int l0 = blockIdx.x * 128;   // N tile (lip rows)
    const int s0 = blockIdx.y * 128;   // M tile (phoneme rows)

    __shared__ float As[2][8][132];    // [buf][k][m]
    __shared__ float Bs[2][8][132];    // [buf][k][n]

    const int t  = threadIdx.x;
    const int tx = t & 15;             // n micro
    const int ty = t >> 4;             // m micro
    const int lr = t >> 1;             // 0..127 row for global loads
    const int lc = (t & 1) * 4;        // k sub-offset (0 or 4)

    const float* Ap = phon + ((size_t)(b * TS + s0 + lr) * DD) + lc;
    const float* Bp = lip  + ((size_t)(b * TL + l0 + lr) * DD) + lc;

    float acc[8][8];
#pragma unroll
    for (int i = 0; i < 8; i++)
#pragma unroll
        for (int j = 0; j < 8; j++) acc[i][j] = 0.0f;

    {
        float4 av = *(const float4*)(Ap);
        float4 bv = *(const float4*)(Bp);
        As[0][lc + 0][lr] = av.x; As[0][lc + 1][lr] = av.y;
        As[0][lc + 2][lr] = av.z; As[0][lc + 3][lr] = av.w;
        Bs[0][lc + 0][lr] = bv.x; Bs[0][lc + 1][lr] = bv.y;
        Bs[0][lc + 2][lr] = bv.z; Bs[0][lc + 3][lr] = bv.w;
    }
    __syncthreads();

    const int NKT = DD / 8;   // 32 slabs
#pragma unroll 1
    for (int kt = 0; kt < NKT; kt++) {
        float4 av, bv;
        const bool more = (kt + 1 < NKT);
        if (more) {
            av = *(const float4*)(Ap + (kt + 1) * 8);
            bv = *(const float4*)(Bp + (kt + 1) * 8);
        }
        const int cur = kt & 1;
#pragma unroll
        for (int k = 0; k < 8; k++) {
            float a[8], bb[8];
            *(float4*)&a[0]  = *(const float4*)&As[cur][k][ty * 4];
            *(float4*)&a[4]  = *(const float4*)&As[cur][k][64 + ty * 4];
            *(float4*)&bb[0] = *(const float4*)&Bs[cur][k][tx * 4];
            *(float4*)&bb[4] = *(const float4*)&Bs[cur][k][64 + tx * 4];
#pragma unroll
            for (int i = 0; i < 8; i++)
#pragma unroll
                for (int j = 0; j < 8; j++) acc[i][j] += a[i] * bb[j];
        }
        if (more) {
            const int nxt = cur ^ 1;
            As[nxt][lc + 0][lr] = av.x; As[nxt][lc + 1][lr] = av.y;
            As[nxt][lc + 2][lr] = av.z; As[nxt][lc + 3][lr] = av.w;
            Bs[nxt][lc + 0][lr] = bv.x; Bs[nxt][lc + 1][lr] = bv.y;
            Bs[nxt][lc + 2][lr] = bv.z; Bs[nxt][lc + 3][lr] = bv.w;
            __syncthreads();
        }
    }

    int mrow[8], ncol[8];
#pragma unroll
    for (int i = 0; i < 4; i++) { mrow[i] = ty * 4 + i; mrow[i + 4] = 64 + ty * 4 + i; }
#pragma unroll
    for (int j = 0; j < 4; j++) { ncol[j] = tx * 4 + j; ncol[j + 4] = 64 + tx * 4 + j; }

    float fa[8], fb[8];
#pragma unroll
    for (int i = 0; i < 8; i++) fa[i] = g_ft[b * TS + s0 + mrow[i]];
#pragma unroll
    for (int j = 0; j < 8; j++) fb[j] = g_invlip[b * TL + l0 + ncol[j]];
#pragma unroll
    for (int i = 0; i < 8; i++)
#pragma unroll
        for (int j = 0; j < 8; j++) acc[i][j] = acc[i][j] * fa[i] * fb[j];

    // sim [b, s, l]
#pragma unroll
    for (int i = 0; i < 8; i++) {
        float* row = sim + ((size_t)(b * TS + s0 + mrow[i]) * TL) + l0;
        *(float4*)(row + tx * 4)      = make_float4(acc[i][0], acc[i][1], acc[i][2], acc[i][3]);
        *(float4*)(row + 64 + tx * 4) = make_float4(acc[i][4], acc[i][5], acc[i][6], acc[i][7]);
    }
    // simT [b, l, s]
#pragma unroll
    for (int j = 0; j < 8; j++) {
        float* row = g_simT + ((size_t)(b * TL + l0 + ncol[j]) * TS) + s0;
        *(float4*)(row + ty * 4)      = make_float4(acc[0][j], acc[1][j], acc[2][j], acc[3][j]);
        *(float4*)(row + 64 + ty * 4) = make_float4(acc[4][j], acc[5][j], acc[6][j], acc[7][j]);
    }
}

// ---------------- monotonic alignment search: warp-specialized, 1 CTA per batch ----------------
// smem layout (bytes):
//   [0, 131072)        dirs  : ushort, layout (j>>3)*256 + lane*8 + (j&7)
//   [131072, 196608)   ring  : float[32][512], XOR-swizzled float4s
//   [196608, 196736)   flags : int[32]
//   [196736, 196740)   consumed
//   [196752, 198800)   hist  : unsigned[512]
#define DP_SMEM 198800
#define RING 32

__device__ __forceinline__ int swz(int p) { return p ^ ((p >> 3) & 7); }

__global__ __launch_bounds__(512) void dp_kernel(const int* __restrict__ src_lens,
                                                 const int* __restrict__ lip_lens,
                                                 float* __restrict__ out_dpred) {
    extern __shared__ char smem[];
    unsigned short* dirs = (unsigned short*)smem;
    float4* ringf4 = (float4*)(smem + 131072);
    volatile int* flags = (volatile int*)(smem + 196608);
    volatile int* consumed = (volatile int*)(smem + 196736);
    unsigned* hist = (unsigned*)(smem + 196752);

    const int b = blockIdx.x;
    const int tid = threadIdx.x;
    const int w = tid >> 5;
    const int lane = tid & 31;
    const int srcLen = src_lens[b];
    const int lipLen = lip_lens[b];

    if (tid < RING) flags[tid] = -1;
    if (tid == 0) *consumed = 0;
    for (int i = tid; i < TS; i += 512) hist[i] = 0;
    __syncthreads();

    const float4* rowbase = (const float4*)(g_simT + (size_t)b * TL * TS);

    if (w > 0) {
        // ---- producers: stream rows [0, lipLen) into the ring, pre-masked ----
        for (int j = w - 1; j < lipLen; j += 15) {
            while (j - *consumed >= RING) __nanosleep(64);
            float4 v[4];
#pragma unroll
            for (int q = 0; q < 4; q++) {
                float4 tv = rowbase[(size_t)j * 128 + lane + q * 32];
                const int fx = (lane + q * 32) * 4;
                if (fx + 0 >= srcLen) tv.x = 0.0f;
                if (fx + 1 >= srcLen) tv.y = 0.0f;
                if (fx + 2 >= srcLen) tv.z = 0.0f;
                if (fx + 3 >= srcLen) tv.w = 0.0f;
                v[q] = tv;
            }
            const int sb = (j & (RING - 1)) * 128;
#pragma unroll
            for (int q = 0; q < 4; q++)
                ringf4[sb + swz(lane + q * 32)] = v[q];
            __threadfence_block();
            __syncwarp();
            if (lane == 0) flags[j & (RING - 1)] = j;
        }
    } else {
        // ---- consumer: DP recurrence out of the ring ----
        float v[16];
#pragma unroll
        for (int k = 0; k < 16; k++) v[k] = 0.0f;
        const int xb = lane * 16;

        for (int j = 0; j < lipLen; j++) {
            const int slot = j & (RING - 1);
            while (flags[slot] != j) { }
            const int sb = slot * 128;
            float4 c0 = ringf4[sb + swz(lane * 4 + 0)];
            float4 c1 = ringf4[sb + swz(lane * 4 + 1)];
            float4 c2 = ringf4[sb + swz(lane * 4 + 2)];
            float4 c3 = ringf4[sb + swz(lane * 4 + 3)];
            float val[16];
            val[0] = c0.x; val[1] = c0.y; val[2]  = c0.z; val[3]  = c0.w;
            val[4] = c1.x; val[5] = c1.y; val[6]  = c1.z; val[7]  = c1.w;
            val[8] = c2.x; val[9] = c2.y; val[10] = c2.z; val[11] = c2.w;
            val[12] = c3.x; val[13] = c3.y; val[14] = c3.z; val[15] = c3.w;

            const float up = __shfl_up_sync(0xffffffffu, v[15], 1);
            float pv = (lane == 0) ? NEGV : up;
            unsigned bits = 0;
            const int tj = j - xb;
#pragma unroll
            for (int k = 0; k < 16; k++) {
                const float cur = v[k];
                const bool stay = (cur >= pv);
                const float vm = stay ? cur : pv;
                float nv = vm + val[k];
                nv = (k <= tj) ? nv : NEGV;
                bits |= (stay ? 1u : 0u) << k;
                pv = cur;
                v[k] = nv;
            }
            dirs[(j >> 3) * 256 + lane * 8 + (j & 7)] = (unsigned short)bits;
            __syncwarp();
            if (lane == 0) *consumed = j + 1;
        }
        __syncwarp();

        // ---- backtrack (lane 0), 8 rows per uint4 ----
        if (lane == 0) {
            int idx = srcLen - 1;
            int cnt = 0;
            int* gi = g_idx + b * TL;
            for (int g = TL / 8 - 1; g >= 0; g--) {
                const int W0 = idx >> 4;
                const uint4 w0 = *(const uint4*)&dirs[g * 256 + W0 * 8];
                const uint4 w1 = (W0 > 0) ? *(const uint4*)&dirs[g * 256 + (W0 - 1) * 8] : w0;
#pragma unroll
                for (int r = 7; r >= 0; r--) {
                    const int j = g * 8 + r;
                    gi[j] = idx;
                    if (j < lipLen) {
                        cnt++;
                        const unsigned cw = ((idx >> 4) == W0)
                            ? ((const unsigned*)&w0)[r >> 1]
                            : ((const unsigned*)&w1)[r >> 1];
                        const unsigned word = (cw >> ((r & 1) * 16)) & 0xffffu;
                        if (!((word >> (idx & 15)) & 1u)) {
                            hist[idx] = (unsigned)cnt;
                            cnt = 0;
                            idx--;
                        }
                    }
                }
            }
            if (idx >= 0) hist[idx] = (unsigned)cnt;
        }
        __syncwarp();

        const float mc = g_meancof;
        for (int x = lane; x < TS; x += 32)
            out_dpred[b * TS + x] = (float)hist[x] * mc;
    }
}

// ---------------- fill gt_similarity and alignment ----------------
__global__ __launch_bounds__(256) void fill_kernel(const int* __restrict__ lip_lens,
                                                   float* __restrict__ gt,
                                                   float* __restrict__ align) {
    const int b = blockIdx.z;
    const int s = blockIdx.y;
    const int l = (blockIdx.x * 256 + threadIdx.x) * 4;
    const int bg = g_begins[b * TS + s];
    const int en = g_ends[b * TS + s];
    const int lipLen = lip_lens[b];
    const int4 iv = *(const int4*)(g_idx + b * TL + l);

    float4 gq, aq;
    gq.x = (l + 0 >= bg && l + 0 < en) ? 1.0f : 0.0f;
    gq.y = (l + 1 >= bg && l + 1 < en) ? 1.0f : 0.0f;
    gq.z = (l + 2 >= bg && l + 2 < en) ? 1.0f : 0.0f;
    gq.w = (l + 3 >= bg && l + 3 < en) ? 1.0f : 0.0f;
    aq.x = (l + 0 < lipLen && iv.x == s) ? 1.0f : 0.0f;
    aq.y = (l + 1 < lipLen && iv.y == s) ? 1.0f : 0.0f;
    aq.z = (l + 2 < lipLen && iv.z == s) ? 1.0f : 0.0f;
    aq.w = (l + 3 < lipLen && iv.w == s) ? 1.0f : 0.0f;

    const size_t off = ((size_t)(b * TS + s) * TL) + l;
    *(float4*)(gt + off) = gq;
    *(float4*)(align + off) = aq;
}

// ---------------- launch ----------------
extern "C" void kernel_launch(void* const* d_in, const int* in_sizes, int n_in,
                              void* d_out, int out_size) {
    const float* lip  = (const float*)d_in[0];
    const float* phon = (const float*)d_in[1];
    const int*   dtg  = (const int*)d_in[2];
    const int*   srcl = (const int*)d_in[3];
    const int*   lipl = (const int*)d_in[4];

    float* out = (float*)d_out;
    const size_t big = (size_t)BB * TS * TL;
    float* sim = out;
    float* gt  = out + big;
    float* al  = out + 2 * big;
    float* dp  = out + 3 * big;

    cudaFuncSetAttribute(dp_kernel, cudaFuncAttributeMaxDynamicSharedMemorySize, 204800);

    stats_kernel<<<BB, TS>>>(dtg, lipl);
    meancof_kernel<<<1, 32>>>();
    lipnorm_kernel<<<(BB * TL) / 8, 256>>>(lip);
    textnorm_kernel<<<(BB * TS) / 8, 256>>>(phon);
    gemm_kernel<<<dim3(TL / 128, TS / 128, BB), 256>>>(lip, phon, sim);
    dp_kernel<<<BB, 512, DP_SMEM>>>(srcl, lipl, dp);
    fill_kernel<<<dim3(TL / 1024, TS, BB), 256>>>(lipl, gt, al);
}